// round 1
// baseline (speedup 1.0000x reference)
#include <cuda_runtime.h>
#include <cuda_bf16.h>

// Problem constants
#define BB 8
#define SS 2048
#define FF 256
#define HH 8
#define DD 64
#define PROJ 512           // HH*DD
#define NCHUNK 16          // s-chunks for weighted-sum partials
#define CHUNK (SS/NCHUNK)  // 128

// Scratch (device globals — no allocation allowed)
__device__ float g_p[BB * HH * FF];            // p[b][h][f] = Wk_h @ q_last  (16K floats)
__device__ float g_w[BB * HH * SS];            // scores -> softmax weights   (512KB)
__device__ float g_part[BB * NCHUNK * HH * FF];// partial weighted x sums     (1MB)

// -------------------------------------------------------------------------
// K1: q_last[b,:] = x[b,S-1,:] @ Wq ; p[b,h,f] = sum_d Wk[f, h*64+d] * q[h*64+d]
// grid: BB blocks, 512 threads
// -------------------------------------------------------------------------
__global__ void k_prep(const float* __restrict__ x,
                       const float* __restrict__ Wq,
                       const float* __restrict__ Wk) {
    int b = blockIdx.x, t = threadIdx.x;
    __shared__ float xs[FF];
    __shared__ float qs[PROJ];

    if (t < FF) xs[t] = x[((size_t)b * SS + (SS - 1)) * FF + t];
    __syncthreads();

    // q_last: thread t -> column c=t of Wq (coalesced across threads)
    float acc = 0.f;
    #pragma unroll 8
    for (int f = 0; f < FF; ++f) acc += xs[f] * Wq[f * PROJ + t];
    qs[t] = acc;
    __syncthreads();

    // p[h][f]: warp-per-output, 64-length dot, coalesced lane loads
    int warp = t >> 5, lane = t & 31;
    for (int i = warp; i < HH * FF; i += 16) {   // 16 warps
        int h = i >> 8;          // i / 256
        int f = i & 255;
        const float* wk = Wk + (size_t)f * PROJ + h * DD;
        float v = wk[lane] * qs[h * DD + lane] + wk[32 + lane] * qs[h * DD + 32 + lane];
        #pragma unroll
        for (int o = 16; o; o >>= 1) v += __shfl_xor_sync(0xFFFFFFFFu, v, o);
        if (lane == 0) g_p[(b * HH + h) * FF + f] = v;
    }
}

// -------------------------------------------------------------------------
// K2: score[b,h,s] = (x[b,s,:] . p[b,h,:]) / 8
// grid: BB*64 blocks (32 rows each), 256 threads (8 warps, warp-per-row)
// -------------------------------------------------------------------------
__global__ void k_scores(const float* __restrict__ x) {
    int blk = blockIdx.x;
    int b = blk >> 6;
    int chunk = blk & 63;
    int t = threadIdx.x;
    __shared__ float ps[HH * FF];   // 8KB

    for (int i = t; i < HH * FF; i += 256) ps[i] = g_p[b * HH * FF + i];
    __syncthreads();

    int warp = t >> 5, lane = t & 31;
    const float4* ps4 = (const float4*)ps;

    for (int r = warp; r < 32; r += 8) {
        int s = chunk * 32 + r;
        const float4* xr = (const float4*)(x + ((size_t)b * SS + s) * FF);
        float4 a = xr[lane];
        float4 c = xr[32 + lane];
        float dot[HH];
        #pragma unroll
        for (int h = 0; h < HH; ++h) {
            float4 pa = ps4[h * 64 + lane];
            float4 pc = ps4[h * 64 + 32 + lane];
            dot[h] = a.x * pa.x + a.y * pa.y + a.z * pa.z + a.w * pa.w
                   + c.x * pc.x + c.y * pc.y + c.z * pc.z + c.w * pc.w;
        }
        #pragma unroll
        for (int h = 0; h < HH; ++h) {
            #pragma unroll
            for (int o = 16; o; o >>= 1)
                dot[h] += __shfl_xor_sync(0xFFFFFFFFu, dot[h], o);
        }
        if (lane == 0) {
            #pragma unroll
            for (int h = 0; h < HH; ++h)
                g_w[((size_t)(b * HH + h)) * SS + s] = dot[h] * 0.125f;
        }
    }
}

// -------------------------------------------------------------------------
// K3: softmax over S per (b,h), in-place on g_w
// grid: BB*HH = 64 blocks, 256 threads (each handles 8 strided elements)
// -------------------------------------------------------------------------
__global__ void k_softmax() {
    int bh = blockIdx.x, t = threadIdx.x;
    float* row = g_w + (size_t)bh * SS;
    float v[8];
    float m = -1e30f;
    #pragma unroll
    for (int i = 0; i < 8; ++i) { v[i] = row[t + i * 256]; m = fmaxf(m, v[i]); }

    __shared__ float sm[8];
    #pragma unroll
    for (int o = 16; o; o >>= 1) m = fmaxf(m, __shfl_xor_sync(0xFFFFFFFFu, m, o));
    if ((t & 31) == 0) sm[t >> 5] = m;
    __syncthreads();
    m = sm[0];
    #pragma unroll
    for (int i = 1; i < 8; ++i) m = fmaxf(m, sm[i]);

    float s = 0.f;
    #pragma unroll
    for (int i = 0; i < 8; ++i) { v[i] = __expf(v[i] - m); s += v[i]; }

    __shared__ float ssum[8];
    #pragma unroll
    for (int o = 16; o; o >>= 1) s += __shfl_xor_sync(0xFFFFFFFFu, s, o);
    if ((t & 31) == 0) ssum[t >> 5] = s;
    __syncthreads();
    s = ssum[0];
    #pragma unroll
    for (int i = 1; i < 8; ++i) s += ssum[i];
    float inv = 1.f / s;
    #pragma unroll
    for (int i = 0; i < 8; ++i) row[t + i * 256] = v[i] * inv;
}

// -------------------------------------------------------------------------
// K4: partial y: part[b,chunk,h,f] = sum_{s in chunk} w[b,h,s] * x[b,s,f]
// grid: BB*NCHUNK = 128 blocks, 256 threads (thread t owns f=t, 8 head accs)
// -------------------------------------------------------------------------
__global__ void k_wsum(const float* __restrict__ x) {
    int blk = blockIdx.x;
    int b = blk >> 4;
    int chunk = blk & 15;
    int t = threadIdx.x;
    __shared__ float ws[HH * CHUNK];   // 4KB

    for (int i = t; i < HH * CHUNK; i += 256) {
        int h = i >> 7;          // i / CHUNK
        int s = i & (CHUNK - 1);
        ws[i] = g_w[((size_t)(b * HH + h)) * SS + chunk * CHUNK + s];
    }
    __syncthreads();

    float acc[HH];
    #pragma unroll
    for (int h = 0; h < HH; ++h) acc[h] = 0.f;

    const float* xp = x + ((size_t)b * SS + chunk * CHUNK) * FF + t;
    #pragma unroll 4
    for (int s = 0; s < CHUNK; ++s) {
        float xv = xp[(size_t)s * FF];
        #pragma unroll
        for (int h = 0; h < HH; ++h) acc[h] += ws[h * CHUNK + s] * xv;
    }

    float* out = g_part + ((size_t)(b * NCHUNK + chunk)) * (HH * FF);
    #pragma unroll
    for (int h = 0; h < HH; ++h) out[h * FF + t] = acc[h];
}

// -------------------------------------------------------------------------
// K5: y = reduce(part); attn[c] = sum_f y[h,f]*Wv[f,c]; out = attn @ Wo + bo
// grid: BB blocks, 512 threads
// -------------------------------------------------------------------------
__global__ void k_out(const float* __restrict__ Wv,
                      const float* __restrict__ Wo,
                      const float* __restrict__ bo,
                      float* __restrict__ out) {
    int b = blockIdx.x, t = threadIdx.x;
    __shared__ float ys[HH * FF];     // 8KB
    __shared__ float attn[PROJ];
    __shared__ float half_out[512];

    const float* pp = g_part + (size_t)b * NCHUNK * (HH * FF);
    for (int i = t; i < HH * FF; i += 512) {
        float s = 0.f;
        #pragma unroll
        for (int c = 0; c < NCHUNK; ++c) s += pp[c * (HH * FF) + i];
        ys[i] = s;
    }
    __syncthreads();

    {   // attn[c], c = t (512 outputs, 512 threads)
        int c = t, h = c >> 6;
        const float* yh = ys + h * FF;
        float a = 0.f;
        #pragma unroll 8
        for (int f = 0; f < FF; ++f) a += yh[f] * Wv[(size_t)f * PROJ + c];
        attn[c] = a;
    }
    __syncthreads();

    {   // out[b,j] split: two halves of the c-sum per output j
        int j = t & 255, half = t >> 8;
        const float* wp = Wo + (size_t)(half * 256) * FF + j;
        const float* ap = attn + half * 256;
        float o = 0.f;
        #pragma unroll 8
        for (int c = 0; c < 256; ++c) o += ap[c] * wp[(size_t)c * FF];
        half_out[t] = o;
    }
    __syncthreads();
    if (t < 256) out[b * FF + t] = half_out[t] + half_out[t + 256] + bo[t];
}

// -------------------------------------------------------------------------
extern "C" void kernel_launch(void* const* d_in, const int* in_sizes, int n_in,
                              void* d_out, int out_size) {
    const float* x  = (const float*)d_in[0];
    const float* Wq = (const float*)d_in[1];
    const float* Wk = (const float*)d_in[2];
    const float* Wv = (const float*)d_in[3];
    const float* Wo = (const float*)d_in[4];
    const float* bo = (const float*)d_in[5];
    float* out = (float*)d_out;

    k_prep<<<BB, 512>>>(x, Wq, Wk);
    k_scores<<<BB * 64, 256>>>(x);
    k_softmax<<<BB * HH, 256>>>();
    k_wsum<<<BB * NCHUNK, 256>>>(x);
    k_out<<<BB, 512>>>(Wv, Wo, bo, out);
}

// round 2
// speedup vs baseline: 2.6004x; 2.6004x over previous
#include <cuda_runtime.h>
#include <cuda_bf16.h>

// Problem constants
#define BB 8
#define SS 2048
#define FF 256
#define HH 8
#define DD 64
#define PROJ 512           // HH*DD
#define NCHUNK 32          // s-chunks for weighted-sum partials
#define CHUNK (SS/NCHUNK)  // 64

// Scratch (device globals — no allocation allowed)
__device__ float g_p[BB * HH * FF];             // p[b][h][f] = Wk_h @ q_last
__device__ float g_w[BB * HH * SS];             // scores -> softmax weights
__device__ float g_part[BB * NCHUNK * HH * FF]; // partial weighted x sums (8MB)
__device__ float g_attn[BB * PROJ];             // attn concat per batch

// -------------------------------------------------------------------------
// K1: per (b,h): q_h = x[b,S-1,:] @ Wq[:,h*64:h*64+64];
//               p[b,h,f] = sum_d Wk[f, h*64+d] * q_h[d]
// grid: BB*HH = 64 blocks, 512 threads
// -------------------------------------------------------------------------
__global__ void k_prep(const float* __restrict__ x,
                       const float* __restrict__ Wq,
                       const float* __restrict__ Wk) {
    int blk = blockIdx.x;
    int b = blk >> 3, h = blk & 7;
    int t = threadIdx.x;
    __shared__ float xs[FF];
    __shared__ float qred[8 * DD];
    __shared__ float qs[DD];

    if (t < FF) xs[t] = x[((size_t)b * SS + (SS - 1)) * FF + t];
    __syncthreads();

    // q_h[d]: 512 threads = 64 d x 8 f-parts of 32
    {
        int d = t & 63, part = t >> 6;
        const float* wq = Wq + (size_t)(part * 32) * PROJ + h * DD + d;
        const float* xf = xs + part * 32;
        float a = 0.f;
        #pragma unroll
        for (int f = 0; f < 32; ++f) a += xf[f] * wq[(size_t)f * PROJ];
        qred[part * DD + d] = a;
    }
    __syncthreads();
    if (t < DD) {
        float s = 0.f;
        #pragma unroll
        for (int p = 0; p < 8; ++p) s += qred[p * DD + t];
        qs[t] = s;
    }
    __syncthreads();

    // p[f]: warp-per-f, 16 warps x 16 f each
    int warp = t >> 5, lane = t & 31;
    float q0 = qs[lane], q1 = qs[32 + lane];
    #pragma unroll 4
    for (int i = 0; i < 16; ++i) {
        int f = warp + 16 * i;
        const float* wk = Wk + (size_t)f * PROJ + h * DD;
        float v = wk[lane] * q0 + wk[32 + lane] * q1;
        #pragma unroll
        for (int o = 16; o; o >>= 1) v += __shfl_xor_sync(0xFFFFFFFFu, v, o);
        if (lane == 0) g_p[(b * HH + h) * FF + f] = v;
    }
}

// -------------------------------------------------------------------------
// K2: score[b,h,s] = (x[b,s,:] . p[b,h,:]) / 8
// grid: BB*64 blocks (32 rows each), 256 threads (8 warps, 4 rows per warp)
// -------------------------------------------------------------------------
__global__ void k_scores(const float* __restrict__ x) {
    int blk = blockIdx.x;
    int b = blk >> 6;
    int chunk = blk & 63;
    int t = threadIdx.x;
    __shared__ float ps[HH * FF];   // 8KB

    for (int i = t; i < HH * FF; i += 256) ps[i] = g_p[b * HH * FF + i];
    __syncthreads();

    int warp = t >> 5, lane = t & 31;
    const float4* ps4 = (const float4*)ps;

    int s0 = chunk * 32 + warp * 4;
    const float4* xr = (const float4*)(x + ((size_t)b * SS + s0) * FF);

    // prefetch all 8 float4 loads (4 rows x 2 halves) -> MLP 8
    float4 a[4], c[4];
    #pragma unroll
    for (int r = 0; r < 4; ++r) {
        a[r] = xr[r * 64 + lane];
        c[r] = xr[r * 64 + 32 + lane];
    }

    #pragma unroll
    for (int r = 0; r < 4; ++r) {
        float dot[HH];
        #pragma unroll
        for (int h = 0; h < HH; ++h) {
            float4 pa = ps4[h * 64 + lane];
            float4 pc = ps4[h * 64 + 32 + lane];
            dot[h] = a[r].x * pa.x + a[r].y * pa.y + a[r].z * pa.z + a[r].w * pa.w
                   + c[r].x * pc.x + c[r].y * pc.y + c[r].z * pc.z + c[r].w * pc.w;
        }
        #pragma unroll
        for (int h = 0; h < HH; ++h) {
            #pragma unroll
            for (int o = 16; o; o >>= 1)
                dot[h] += __shfl_xor_sync(0xFFFFFFFFu, dot[h], o);
        }
        if (lane == 0) {
            int s = s0 + r;
            #pragma unroll
            for (int h = 0; h < HH; ++h)
                g_w[((size_t)(b * HH + h)) * SS + s] = dot[h] * 0.125f;
        }
    }
}

// -------------------------------------------------------------------------
// K3: softmax over S per (b,h), in-place on g_w
// grid: BB*HH = 64 blocks, 256 threads
// -------------------------------------------------------------------------
__global__ void k_softmax() {
    int bh = blockIdx.x, t = threadIdx.x;
    float* row = g_w + (size_t)bh * SS;
    float v[8];
    float m = -1e30f;
    #pragma unroll
    for (int i = 0; i < 8; ++i) { v[i] = row[t + i * 256]; m = fmaxf(m, v[i]); }

    __shared__ float sm[8];
    #pragma unroll
    for (int o = 16; o; o >>= 1) m = fmaxf(m, __shfl_xor_sync(0xFFFFFFFFu, m, o));
    if ((t & 31) == 0) sm[t >> 5] = m;
    __syncthreads();
    m = sm[0];
    #pragma unroll
    for (int i = 1; i < 8; ++i) m = fmaxf(m, sm[i]);

    float s = 0.f;
    #pragma unroll
    for (int i = 0; i < 8; ++i) { v[i] = __expf(v[i] - m); s += v[i]; }

    __shared__ float ssum[8];
    #pragma unroll
    for (int o = 16; o; o >>= 1) s += __shfl_xor_sync(0xFFFFFFFFu, s, o);
    if ((t & 31) == 0) ssum[t >> 5] = s;
    __syncthreads();
    s = ssum[0];
    #pragma unroll
    for (int i = 1; i < 8; ++i) s += ssum[i];
    float inv = 1.f / s;
    #pragma unroll
    for (int i = 0; i < 8; ++i) row[t + i * 256] = v[i] * inv;
}

// -------------------------------------------------------------------------
// K4: part[b,chunk,h,f] = sum_{s in chunk} w[b,h,s] * x[b,s,f]
// grid: BB*NCHUNK = 256 blocks, 256 threads
// thread owns float4 f4 = t&63; s-group sg = t>>6 (4 groups x 16 s)
// -------------------------------------------------------------------------
__global__ void k_wsum(const float* __restrict__ x) {
    int blk = blockIdx.x;
    int b = blk >> 5;
    int chunk = blk & 31;
    int t = threadIdx.x;
    __shared__ float ws[HH * CHUNK];       // 2KB
    __shared__ float4 red[3 * 8 * 64];     // 24KB

    for (int i = t; i < HH * CHUNK; i += 256) {
        int h = i >> 6;               // i / CHUNK
        int s = i & (CHUNK - 1);
        ws[i] = g_w[((size_t)(b * HH + h)) * SS + chunk * CHUNK + s];
    }
    __syncthreads();

    int f4 = t & 63, sg = t >> 6;

    float4 acc[HH];
    #pragma unroll
    for (int h = 0; h < HH; ++h) acc[h] = make_float4(0.f, 0.f, 0.f, 0.f);

    const float4* xp = (const float4*)(x + ((size_t)b * SS + chunk * CHUNK) * FF);
    #pragma unroll 4
    for (int i = 0; i < 16; ++i) {
        int s = sg * 16 + i;
        float4 xv = xp[(size_t)s * 64 + f4];
        #pragma unroll
        for (int h = 0; h < HH; ++h) {
            float w = ws[h * CHUNK + s];
            acc[h].x += w * xv.x; acc[h].y += w * xv.y;
            acc[h].z += w * xv.z; acc[h].w += w * xv.w;
        }
    }

    if (sg > 0) {
        #pragma unroll
        for (int h = 0; h < HH; ++h) red[(sg - 1) * 512 + h * 64 + f4] = acc[h];
    }
    __syncthreads();
    if (sg == 0) {
        float4* out4 = (float4*)(g_part + ((size_t)(b * NCHUNK + chunk)) * (HH * FF));
        #pragma unroll
        for (int h = 0; h < HH; ++h) {
            float4 r = acc[h];
            #pragma unroll
            for (int g = 0; g < 3; ++g) {
                float4 o = red[g * 512 + h * 64 + f4];
                r.x += o.x; r.y += o.y; r.z += o.z; r.w += o.w;
            }
            out4[h * 64 + f4] = r;
        }
    }
}

// -------------------------------------------------------------------------
// K5: per (b,h): y[f] = reduce partials; attn[h*64+d] = sum_f y[f]*Wv[f,h*64+d]
// grid: BB*HH = 64 blocks, 512 threads
// -------------------------------------------------------------------------
__global__ void k_attn(const float* __restrict__ Wv) {
    int blk = blockIdx.x;
    int b = blk >> 3, h = blk & 7;
    int t = threadIdx.x;
    __shared__ float ys[FF];
    __shared__ float ared[8 * DD];

    if (t < FF) {
        const float* pp = g_part + (size_t)b * NCHUNK * (HH * FF) + h * FF + t;
        float s = 0.f;
        #pragma unroll
        for (int c = 0; c < NCHUNK; ++c) s += pp[(size_t)c * (HH * FF)];
        ys[t] = s;
    }
    __syncthreads();

    // attn: 512 threads = 64 d x 8 f-parts of 32
    {
        int d = t & 63, part = t >> 6;
        const float* wv = Wv + (size_t)(part * 32) * PROJ + h * DD + d;
        const float* yf = ys + part * 32;
        float a = 0.f;
        #pragma unroll
        for (int f = 0; f < 32; ++f) a += yf[f] * wv[(size_t)f * PROJ];
        ared[part * DD + d] = a;
    }
    __syncthreads();
    if (t < DD) {
        float s = 0.f;
        #pragma unroll
        for (int p = 0; p < 8; ++p) s += ared[p * DD + t];
        g_attn[b * PROJ + h * DD + t] = s;
    }
}

// -------------------------------------------------------------------------
// K6: out[b,j] = sum_c attn[b,c] * Wo[c,j] + bo[j]
// grid: BB*4 = 32 blocks (64 j each), 512 threads
// -------------------------------------------------------------------------
__global__ void k_final(const float* __restrict__ Wo,
                        const float* __restrict__ bo,
                        float* __restrict__ out) {
    int blk = blockIdx.x;
    int b = blk >> 2, jblk = blk & 3;
    int t = threadIdx.x;
    __shared__ float as[PROJ];
    __shared__ float ored[8 * 64];

    if (t < PROJ) as[t] = g_attn[b * PROJ + t];
    __syncthreads();

    {
        int j = jblk * 64 + (t & 63);
        int part = t >> 6;   // 8 parts x 64 c
        const float* wo = Wo + (size_t)(part * 64) * FF + j;
        const float* ap = as + part * 64;
        float o = 0.f;
        #pragma unroll
        for (int c = 0; c < 64; ++c) o += ap[c] * wo[(size_t)c * FF];
        ored[part * 64 + (t & 63)] = o;
    }
    __syncthreads();
    if (t < 64) {
        float s = 0.f;
        #pragma unroll
        for (int p = 0; p < 8; ++p) s += ored[p * 64 + t];
        int j = jblk * 64 + t;
        out[b * FF + j] = s + bo[j];
    }
}

// -------------------------------------------------------------------------
extern "C" void kernel_launch(void* const* d_in, const int* in_sizes, int n_in,
                              void* d_out, int out_size) {
    const float* x  = (const float*)d_in[0];
    const float* Wq = (const float*)d_in[1];
    const float* Wk = (const float*)d_in[2];
    const float* Wv = (const float*)d_in[3];
    const float* Wo = (const float*)d_in[4];
    const float* bo = (const float*)d_in[5];
    float* out = (float*)d_out;

    k_prep<<<BB * HH, 512>>>(x, Wq, Wk);
    k_scores<<<BB * 64, 256>>>(x);
    k_softmax<<<BB * HH, 256>>>();
    k_wsum<<<BB * NCHUNK, 256>>>(x);
    k_attn<<<BB * HH, 512>>>(Wv);
    k_final<<<BB * 4, 512>>>(Wo, bo, out);
}